// round 15
// baseline (speedup 1.0000x reference)
#include <cuda_runtime.h>

// GeneralMechanismODE — FINAL (R7 configuration).
//
// Roofline argument (established R1-R14):
//   - 192 MB compulsory traffic per replay (128 MB read + 64 MB write),
//     zero reuse; cross-replay L2 residency disproven (R8).
//   - wall = traffic / achievable mixed-R/W DRAM bandwidth (~6.6-6.7 TB/s
//     on B300 for a 2:1 interleaved stream). Confirmed by R14: best-ever
//     ncu window (23.7us, dense shuffle-exchange accesses) left wall
//     unchanged — in-window gains only phase-shift the .wt drain tail.
//   - config search results: block 128 optimal (256/64 regress), 1 row/
//     thread (multi-row & persistent regress via lost load-front churn),
//     .cs loads + .wt stores best (default L2 policy regresses, v8 256-bit
//     accesses deterministically regress wall), prefetch hints neutral.
//
// This config is the only one observed under 29us (28.7 / 29.4 samples).

__global__ __launch_bounds__(128) void ode_kernel_final(
    const float4* __restrict__ y,    // 2*B float4
    const float4* __restrict__ kf,   // B float4
    const float4* __restrict__ kr,   // B float4
    float4* __restrict__ out,        // 2*B float4
    int B)
{
    int b = blockIdx.x * blockDim.x + threadIdx.x;
    if (b >= B) return;

    // 4 independent 128-bit streaming loads, front-batched.
    float4 ylo = __ldcs(&y[2 * b + 0]);   // y0..y3
    float4 yhi = __ldcs(&y[2 * b + 1]);   // y4..y7
    float4 f   = __ldcs(&kf[b]);
    float4 r   = __ldcs(&kr[b]);

    float v0 = f.x * ylo.x * yhi.x - r.x * ylo.y;          // kf0*E*A  - kr0*EA
    float v1 = f.y * ylo.y * yhi.y - r.y * ylo.w;          // kf1*EA*B - kr1*EAB
    float v2 = f.z * ylo.w         - r.z * ylo.z * yhi.z;  // kf2*EAB  - kr2*EQ*P
    float v3 = f.w * ylo.z         - r.w * ylo.x * yhi.w;  // kf3*EQ   - kr3*E*Q

    float4 olo, ohi;
    olo.x = v3 - v0;   // dE
    olo.y = v0 - v1;   // dEA
    olo.z = v2 - v3;   // dEQ
    olo.w = v1 - v2;   // dEAB
    ohi.x = -v0;       // dA
    ohi.y = -v1;       // dB
    ohi.z = v2;        // dP
    ohi.w = v3;        // dQ

    __stwt(&out[2 * b + 0], olo);
    __stwt(&out[2 * b + 1], ohi);
}

extern "C" void kernel_launch(void* const* d_in, const int* in_sizes, int n_in,
                              void* d_out, int out_size)
{
    // metadata order: t (1), y (B*8), forward_rates (B*4), reverse_rates (B*4)
    const float4* y  = (const float4*)d_in[1];
    const float4* kf = (const float4*)d_in[2];
    const float4* kr = (const float4*)d_in[3];
    float4* out = (float4*)d_out;

    int B = in_sizes[1] / 8;
    const int threads = 128;
    int blocks = (B + threads - 1) / threads;
    ode_kernel_final<<<blocks, threads>>>(y, kf, kr, out, B);
}

// round 16
// speedup vs baseline: 1.0099x; 1.0099x over previous
#include <cuda_runtime.h>

// GeneralMechanismODE — single-touch stream (96 B in, 32 B out per row).
// R16: byte-identical resubmission of R14 (dense shuffle-exchange) for a
// second wall sample. R14's one sample (29.15us) beats the R7-family mean
// (29.3us over 5 samples: 28.7/29.15/29.4/29.4/29.44) and it strictly
// dominates in-window (23.7us, DRAM 73.5%, 8.1 TB/s apparent SM-side).
// Mechanism: warp loads 32 rows as two fully-dense 512 B LDG.128.cs
// (lane-major), SHFL.XOR(1) re-pairs (ylo,yhi) per row; reverse exchange
// before two dense STG.128.wt. Halves LTS sector requests for 160/192 MB
// of traffic vs the row-major layout.

__device__ __forceinline__ float4 shfl_xor1_f4(float4 v) {
    float4 o;
    o.x = __shfl_xor_sync(0xffffffffu, v.x, 1);
    o.y = __shfl_xor_sync(0xffffffffu, v.y, 1);
    o.z = __shfl_xor_sync(0xffffffffu, v.z, 1);
    o.w = __shfl_xor_sync(0xffffffffu, v.w, 1);
    return o;
}

__global__ __launch_bounds__(128) void ode_kernel16(
    const float4* __restrict__ y4,   // 2*B float4
    const float4* __restrict__ kf,   // B float4
    const float4* __restrict__ kr,   // B float4
    float4* __restrict__ out,        // 2*B float4
    int B)
{
    int tid  = blockIdx.x * blockDim.x + threadIdx.x;
    int w    = tid >> 5;          // global warp id: rows 32w .. 32w+31
    int lane = tid & 31;
    bool even = (lane & 1) == 0;

    // This thread's row (after exchange): even lane 2k -> 32w+k, odd -> 32w+16+k
    int row = 32 * w + ((lane & 1) ? 16 : 0) + (lane >> 1);
    if (row >= B) return;  // B % 128 == 0 here, so never taken; kept for safety

    // Dense lane-major loads: each LDG.128 covers 512 contiguous bytes.
    float4 A = __ldcs(&y4[64 * w + lane]);
    float4 Bv = __ldcs(&y4[64 * w + 32 + lane]);
    float4 f = __ldcs(&kf[row]);   // permuted lanes, same 512 B region: dense
    float4 r = __ldcs(&kr[row]);

    // Exchange: even lane sends B (ylo of partner's row), odd sends A (yhi of
    // partner's row); each receives the missing half of its own row.
    float4 recv = shfl_xor1_f4(even ? Bv : A);
    float4 ylo = even ? A    : recv;
    float4 yhi = even ? recv : Bv;

    float v0 = f.x * ylo.x * yhi.x - r.x * ylo.y;          // kf0*E*A  - kr0*EA
    float v1 = f.y * ylo.y * yhi.y - r.y * ylo.w;          // kf1*EA*B - kr1*EAB
    float v2 = f.z * ylo.w         - r.z * ylo.z * yhi.z;  // kf2*EAB  - kr2*EQ*P
    float v3 = f.w * ylo.z         - r.w * ylo.x * yhi.w;  // kf3*EQ   - kr3*E*Q

    float4 olo, ohi;
    olo.x = v3 - v0;   // dE
    olo.y = v0 - v1;   // dEA
    olo.z = v2 - v3;   // dEQ
    olo.w = v1 - v2;   // dEAB
    ohi.x = -v0;       // dA
    ohi.y = -v1;       // dB
    ohi.z = v2;        // dP
    ohi.w = v3;        // dQ

    // Reverse exchange for dense stores:
    // store A slot (fidx 64w+l):    even -> own olo, odd -> partner's ohi
    // store B slot (fidx 64w+32+l): even -> partner's olo, odd -> own ohi
    float4 recv2 = shfl_xor1_f4(even ? ohi : olo);
    float4 stA = even ? olo   : recv2;
    float4 stB = even ? recv2 : ohi;

    __stwt(&out[64 * w + lane], stA);
    __stwt(&out[64 * w + 32 + lane], stB);
}

extern "C" void kernel_launch(void* const* d_in, const int* in_sizes, int n_in,
                              void* d_out, int out_size)
{
    // metadata order: t (1), y (B*8), forward_rates (B*4), reverse_rates (B*4)
    const float4* y  = (const float4*)d_in[1];
    const float4* kf = (const float4*)d_in[2];
    const float4* kr = (const float4*)d_in[3];
    float4* out = (float4*)d_out;

    int B = in_sizes[1] / 8;
    const int threads = 128;
    int blocks = (B + threads - 1) / threads;
    ode_kernel16<<<blocks, threads>>>(y, kf, kr, out, B);
}